// round 12
// baseline (speedup 1.0000x reference)
#include <cuda_runtime.h>
#include <cuda_bf16.h>
#include <math.h>
#include <stdint.h>

// ---------------------------------------------------------------------------
// Problem constants
// ---------------------------------------------------------------------------
#define BATCH 4
#define SEQ   2048
#define DIM   768
#define NTOK  (BATCH * SEQ)          // 8192
#define NTHREADS 256
#define SCALE 0.03608439182435161f   // 1/sqrt(768)

// bf16 GEMM tiling (M GEMM only): 128x128 tile, K chunk 32 bf16, SW64
#define BK 32
#define TILE_B  8192
#define STAGE_B (4 * TILE_B)         // 32 KB
#define SMEM_BYTES (2 * STAGE_B)     // 64 KB

// tf32 tiling: 128x256 CTA tile (warp 64x64), K chunk 32 fp32, SW128
#define BK2 32
#define A_TILE_B   16384             // 128 rows * 128 B
#define B_TILE_B   32768             // 256 rows * 128 B
#define W_STAGE_B  (A_TILE_B + B_TILE_B)   // 48 KB
#define W_SMEM     (2 * W_STAGE_B)         // 96 KB

#define SWZ(o)   ((o) ^ ((((uint32_t)(o)) >> 3) & 0x70))   // SW128
#define SWZ64(o) ((o) ^ ((((uint32_t)(o)) >> 3) & 0x30))   // SW64

// ---------------------------------------------------------------------------
// Scratch (__device__ globals; referenced ONLY from device code)
// ---------------------------------------------------------------------------
__device__ __align__(128) float         g_xt[NTOK * DIM];      // x tf32-rounded
__device__ __align__(128) __nv_bfloat16 g_wqTh[DIM * DIM], g_wqTl[DIM * DIM];
__device__ __align__(128) __nv_bfloat16 g_wkTh[DIM * DIM], g_wkTl[DIM * DIM];
__device__ __align__(128) float         g_wvt[DIM * DIM];      // wv tf32-rounded
__device__ __align__(128) float         g_mt[DIM * DIM];       // Mrow tf32-rounded
__device__ __align__(128) float         g_yt[NTOK * DIM];      // Y tf32-rounded
__device__ __align__(128) float         g_vt[DIM * NTOK];      // V^T tf32-rounded
__device__ __align__(128) float         g_s[(size_t)BATCH * SEQ * SEQ];

// ---------------------------------------------------------------------------
// PTX helpers
// ---------------------------------------------------------------------------
__device__ __forceinline__ uint32_t smem_u32(const void* p) {
    uint32_t a;
    asm("{ .reg .u64 t; cvta.to.shared.u64 t, %1; cvt.u32.u64 %0, t; }"
        : "=r"(a) : "l"(p));
    return a;
}
__device__ __forceinline__ void cp16(uint32_t dst, const void* src) {
    asm volatile("cp.async.cg.shared.global [%0], [%1], 16;" :: "r"(dst), "l"(src));
}
__device__ __forceinline__ void cp_commit() {
    asm volatile("cp.async.commit_group;" ::: "memory");
}
template <int N>
__device__ __forceinline__ void cp_wait() {
    asm volatile("cp.async.wait_group %0;" :: "n"(N) : "memory");
}
__device__ __forceinline__ void ldsm4(uint32_t addr, uint32_t* r) {
    asm volatile("ldmatrix.sync.aligned.m8n8.x4.shared.b16 {%0,%1,%2,%3}, [%4];"
                 : "=r"(r[0]), "=r"(r[1]), "=r"(r[2]), "=r"(r[3]) : "r"(addr));
}
__device__ __forceinline__ void ldsm4_2(uint32_t addr, uint32_t* r0, uint32_t* r1) {
    asm volatile("ldmatrix.sync.aligned.m8n8.x4.shared.b16 {%0,%1,%2,%3}, [%4];"
                 : "=r"(r0[0]), "=r"(r0[1]), "=r"(r1[0]), "=r"(r1[1]) : "r"(addr));
}
__device__ __forceinline__ void ldsm2(uint32_t addr, uint32_t* r) {
    asm volatile("ldmatrix.sync.aligned.m8n8.x2.shared.b16 {%0,%1}, [%2];"
                 : "=r"(r[0]), "=r"(r[1]) : "r"(addr));
}
__device__ __forceinline__ void mma16816(float* d, const uint32_t* a, const uint32_t* b) {
    asm volatile(
        "mma.sync.aligned.m16n8k16.row.col.f32.bf16.bf16.f32 "
        "{%0,%1,%2,%3}, {%4,%5,%6,%7}, {%8,%9}, {%0,%1,%2,%3};"
        : "+f"(d[0]), "+f"(d[1]), "+f"(d[2]), "+f"(d[3])
        : "r"(a[0]), "r"(a[1]), "r"(a[2]), "r"(a[3]), "r"(b[0]), "r"(b[1]));
}
__device__ __forceinline__ void mma1688t(float* d, const uint32_t* a, const uint32_t* b) {
    asm volatile(
        "mma.sync.aligned.m16n8k8.row.col.f32.tf32.tf32.f32 "
        "{%0,%1,%2,%3}, {%4,%5,%6,%7}, {%8,%9}, {%0,%1,%2,%3};"
        : "+f"(d[0]), "+f"(d[1]), "+f"(d[2]), "+f"(d[3])
        : "r"(a[0]), "r"(a[1]), "r"(a[2]), "r"(a[3]), "r"(b[0]), "r"(b[1]));
}
__device__ __forceinline__ float to_tf32(float x) {
    float r;
    asm("cvt.rna.tf32.f32 %0, %1;" : "=f"(r) : "f"(x));
    return r;
}

// ---------------------------------------------------------------------------
// 128x128 NT GEMM tile, split-bf16 3-term, BK=32, SW64.
// Used ONLY for the tiny M GEMM. Epilogue: tf32-rounded fp32 out.
// ---------------------------------------------------------------------------
__device__ __forceinline__ void gemm_core_m(
    const __nv_bfloat16* __restrict__ Ah, const __nv_bfloat16* __restrict__ Al, int lda,
    const __nv_bfloat16* __restrict__ Bh, const __nv_bfloat16* __restrict__ Bl, int ldb,
    int m0, int n0, int nIter,
    float* __restrict__ Of, int ldc)
{
    extern __shared__ char smem[];
    const uint32_t sbase = smem_u32(smem);
    const int tid  = threadIdx.x;
    const int lane = tid & 31;
    const int wid  = tid >> 5;
    const int wm   = wid >> 2;
    const int wn   = wid & 3;

    const __nv_bfloat16* A0h = Ah + (size_t)m0 * lda;
    const __nv_bfloat16* A0l = Al + (size_t)m0 * lda;
    const __nv_bfloat16* B0h = Bh + (size_t)n0 * ldb;
    const __nv_bfloat16* B0l = Bl + (size_t)n0 * ldb;

    auto load_tile = [&](int it) {
        const uint32_t db = sbase + (uint32_t)(it & 1) * STAGE_B;
        const int k0 = it * BK;
#pragma unroll
        for (int i = 0; i < 2; i++) {
            const int c = tid + i * NTHREADS;
            const int row = c >> 2, ch = c & 3;
            const uint32_t so = SWZ64((uint32_t)(row * 64 + ch * 16));
            const size_t ga = (size_t)row * lda + k0 + ch * 8;
            const size_t gb = (size_t)row * ldb + k0 + ch * 8;
            cp16(db + so,              A0h + ga);
            cp16(db + TILE_B + so,     A0l + ga);
            cp16(db + 2 * TILE_B + so, B0h + gb);
            cp16(db + 3 * TILE_B + so, B0l + gb);
        }
        cp_commit();
    };

    float acc[4][4][4];
#pragma unroll
    for (int i = 0; i < 4; i++)
#pragma unroll
        for (int j = 0; j < 4; j++)
#pragma unroll
            for (int v = 0; v < 4; v++) acc[i][j][v] = 0.0f;

    const uint32_t a_l = ((uint32_t)(lane & 15) << 6) + ((uint32_t)(lane >> 4) << 4);
    const uint32_t b_l = ((uint32_t)(lane & 7) << 6) + ((uint32_t)((lane >> 3) & 1) << 4);

    load_tile(0);
    load_tile(1);

    for (int it = 0; it < nIter; ++it) {
        if (it + 1 < nIter) cp_wait<1>(); else cp_wait<0>();
        __syncthreads();

        const uint32_t db = sbase + (uint32_t)(it & 1) * STAGE_B;
#pragma unroll
        for (int ks = 0; ks < 2; ks++) {
            uint32_t ah[4][4], al_[4][4], bh[4][2], bl_[4][2];
#pragma unroll
            for (int fm = 0; fm < 4; fm++) {
                const uint32_t sw = SWZ64(((uint32_t)(wm * 64 + fm * 16) << 6) +
                                          (uint32_t)(ks * 32) + a_l);
                ldsm4(db + sw, ah[fm]);
                ldsm4(db + TILE_B + sw, al_[fm]);
            }
#pragma unroll
            for (int fn = 0; fn < 4; fn++) {
                const uint32_t sw = SWZ64(((uint32_t)(wn * 32 + fn * 8) << 6) +
                                          (uint32_t)(ks * 32) + b_l);
                ldsm2(db + 2 * TILE_B + sw, bh[fn]);
                ldsm2(db + 3 * TILE_B + sw, bl_[fn]);
            }
#pragma unroll
            for (int fm = 0; fm < 4; fm++)
#pragma unroll
                for (int fn = 0; fn < 4; fn++)
                    mma16816(acc[fm][fn], ah[fm], bh[fn]);
#pragma unroll
            for (int fm = 0; fm < 4; fm++)
#pragma unroll
                for (int fn = 0; fn < 4; fn++)
                    mma16816(acc[fm][fn], ah[fm], bl_[fn]);
#pragma unroll
            for (int fm = 0; fm < 4; fm++)
#pragma unroll
                for (int fn = 0; fn < 4; fn++)
                    mma16816(acc[fm][fn], al_[fm], bh[fn]);
        }
        __syncthreads();
        if (it + 2 < nIter) load_tile(it + 2);
    }

    const int er = lane >> 2;
    const int ec = (lane & 3) * 2;
#pragma unroll
    for (int fm = 0; fm < 4; fm++) {
#pragma unroll
        for (int fn = 0; fn < 4; fn++) {
            const int r0 = m0 + wm * 64 + fm * 16 + er;
            const int r1 = r0 + 8;
            const int c  = n0 + wn * 32 + fn * 8 + ec;
            *(float2*)(Of + (size_t)r0 * ldc + c) =
                make_float2(to_tf32(acc[fm][fn][0]), to_tf32(acc[fm][fn][1]));
            *(float2*)(Of + (size_t)r1 * ldc + c) =
                make_float2(to_tf32(acc[fm][fn][2]), to_tf32(acc[fm][fn][3]));
        }
    }
}

// ---------------------------------------------------------------------------
// 128x256 NT GEMM tile, single-term TF32, SW128, warp tile 64x64.
// ldmatrix fragment loads; B pairs packed into ldsm4 (2 fn per instr).
// ROUND 1: round output to tf32.  ROUND 0: plain fp32 out.
// ---------------------------------------------------------------------------
template <int ROUND>
__device__ __forceinline__ void tf32_core(
    const float* __restrict__ A, int lda,
    const float* __restrict__ B, int ldb,
    int m0, int n0, int nIter,
    float* __restrict__ C, int ldc)
{
    extern __shared__ char smem[];
    const uint32_t sbase = smem_u32(smem);
    const int tid  = threadIdx.x;
    const int lane = tid & 31;
    const int wid  = tid >> 5;
    const int wm   = wid >> 2;    // 0..1 -> rows wm*64
    const int wn   = wid & 3;     // 0..3 -> cols wn*64

    const float* A0 = A + (size_t)m0 * lda;
    const float* B0 = B + (size_t)n0 * ldb;

    auto load_tile = [&](int it) {
        const uint32_t db = sbase + (uint32_t)(it & 1) * W_STAGE_B;
        const int k0 = it * BK2;
#pragma unroll
        for (int i = 0; i < 4; i++) {          // A: 1024 chunks
            const int c = tid + i * NTHREADS;
            const int row = c >> 3, ch = c & 7;
            const uint32_t so = SWZ((uint32_t)(row * 128 + ch * 16));
            cp16(db + so, A0 + (size_t)row * lda + k0 + ch * 4);
        }
#pragma unroll
        for (int i = 0; i < 8; i++) {          // B: 2048 chunks (256 rows)
            const int c = tid + i * NTHREADS;
            const int row = c >> 3, ch = c & 7;
            const uint32_t so = SWZ((uint32_t)(row * 128 + ch * 16));
            cp16(db + A_TILE_B + so, B0 + (size_t)row * ldb + k0 + ch * 4);
        }
        cp_commit();
    };

    float acc[4][8][4];
#pragma unroll
    for (int i = 0; i < 4; i++)
#pragma unroll
        for (int j = 0; j < 8; j++)
#pragma unroll
            for (int v = 0; v < 4; v++) acc[i][j][v] = 0.0f;

    // A (ldsm4): lanes 0-15 -> rows r..r+15 col+0; 16-31 -> same rows +16B
    const uint32_t a_l = ((uint32_t)(lane & 15) << 7) + ((uint32_t)(lane >> 4) << 4);
    // B (ldsm4, two fn per instr): lanes 0-7 rows+0 col+0 (m0), 8-15 rows+0
    // col+16 (m1), 16-23 rows+8 col+0 (m2), 24-31 rows+8 col+16 (m3)
    const uint32_t b_l = ((uint32_t)(lane & 7) << 7) +
                         ((uint32_t)((lane >> 3) & 1) << 4) +
                         ((uint32_t)(lane >> 4) << 10);

    load_tile(0);
    load_tile(1);

    for (int it = 0; it < nIter; ++it) {
        if (it + 1 < nIter) cp_wait<1>(); else cp_wait<0>();
        __syncthreads();

        const uint32_t db = sbase + (uint32_t)(it & 1) * W_STAGE_B;
#pragma unroll
        for (int ks = 0; ks < 4; ks++) {
            uint32_t a[4][4], bb[8][2];
#pragma unroll
            for (int fm = 0; fm < 4; fm++) {
                const uint32_t sw = SWZ(((uint32_t)(wm * 64 + fm * 16) << 7) +
                                        (uint32_t)(ks * 32) + a_l);
                ldsm4(db + sw, a[fm]);
            }
#pragma unroll
            for (int fp = 0; fp < 4; fp++) {   // each loads fn=2fp and 2fp+1
                const uint32_t sw = SWZ(((uint32_t)(wn * 64 + fp * 16) << 7) +
                                        (uint32_t)(ks * 32) + b_l);
                ldsm4_2(db + A_TILE_B + sw, bb[2 * fp], bb[2 * fp + 1]);
            }
#pragma unroll
            for (int fm = 0; fm < 4; fm++)
#pragma unroll
                for (int fn = 0; fn < 8; fn++)
                    mma1688t(acc[fm][fn], a[fm], bb[fn]);
        }
        __syncthreads();
        if (it + 2 < nIter) load_tile(it + 2);
    }

    const int er = lane >> 2;
    const int ec = (lane & 3) * 2;
#pragma unroll
    for (int fm = 0; fm < 4; fm++) {
#pragma unroll
        for (int fn = 0; fn < 8; fn++) {
            const int r0 = m0 + wm * 64 + fm * 16 + er;
            const int r1 = r0 + 8;
            const int c  = n0 + wn * 64 + fn * 8 + ec;
            if (ROUND) {
                *(float2*)(C + (size_t)r0 * ldc + c) =
                    make_float2(to_tf32(acc[fm][fn][0]), to_tf32(acc[fm][fn][1]));
                *(float2*)(C + (size_t)r1 * ldc + c) =
                    make_float2(to_tf32(acc[fm][fn][2]), to_tf32(acc[fm][fn][3]));
            } else {
                *(float2*)(C + (size_t)r0 * ldc + c) = make_float2(acc[fm][fn][0], acc[fm][fn][1]);
                *(float2*)(C + (size_t)r1 * ldc + c) = make_float2(acc[fm][fn][2], acc[fm][fn][3]);
            }
        }
    }
}

// ---------------------------------------------------------------------------
// Kernel 0: convert. x -> xt; wv -> wvt (both tf32-rounded fp32).
// ---------------------------------------------------------------------------
#define NX4 (NTOK * DIM / 4)
#define NW4 (DIM * DIM / 4)

__global__ __launch_bounds__(NTHREADS)
void convert_kernel(const float* __restrict__ x, const float* __restrict__ wv)
{
    const int i = blockIdx.x * NTHREADS + threadIdx.x;
    if (i < NX4) {
        const float4 v = ((const float4*)x)[i];
        ((float4*)g_xt)[i] = make_float4(to_tf32(v.x), to_tf32(v.y),
                                         to_tf32(v.z), to_tf32(v.w));
    } else if (i < NX4 + NW4) {
        const int j = i - NX4;
        const float4 v = ((const float4*)wv)[j];
        ((float4*)g_wvt)[j] = make_float4(to_tf32(v.x), to_tf32(v.y),
                                          to_tf32(v.z), to_tf32(v.w));
    }
}

// ---------------------------------------------------------------------------
// Kernel 1: tiled transpose wq, wk -> bf16 hi/lo pairs of W^T.
// ---------------------------------------------------------------------------
__global__ __launch_bounds__(NTHREADS)
void transpose_w_kernel(const float* __restrict__ wq, const float* __restrict__ wk)
{
    __shared__ float t[32][33];
    const float* src = blockIdx.z ? wk : wq;
    __nv_bfloat16* oh = blockIdx.z ? g_wkTh : g_wqTh;
    __nv_bfloat16* ol = blockIdx.z ? g_wkTl : g_wqTl;
    const int tx = threadIdx.x & 31, ty = threadIdx.x >> 5;
    const int c0 = blockIdx.x * 32, r0 = blockIdx.y * 32;
#pragma unroll
    for (int i = 0; i < 4; i++)
        t[ty + i * 8][tx] = src[(size_t)(r0 + ty + i * 8) * DIM + c0 + tx];
    __syncthreads();
#pragma unroll
    for (int i = 0; i < 4; i++) {
        const int d = c0 + ty + i * 8;
        const int e = r0 + tx;
        const float v = t[tx][ty + i * 8];
        const __nv_bfloat16 h = __float2bfloat16(v);
        oh[(size_t)d * DIM + e] = h;
        ol[(size_t)d * DIM + e] = __float2bfloat16(v - __bfloat162float(h));
    }
}

// ---------------------------------------------------------------------------
// Kernel 2: fused V + M.
//   CTA < 192:  V^T = Wv X^T, 128x256 tf32 tiles, out g_vt (tf32-rounded)
//   CTA >= 192: Mrow = Wk^T x Wq^T (3-term bf16), out g_mt
// ---------------------------------------------------------------------------
__global__ __launch_bounds__(NTHREADS, 1)
void vm_kernel()
{
    const int cta = blockIdx.x;
    if (cta < 192) {
        const int mi = cta / 32, ni = cta % 32;   // 6 x 32
        tf32_core<1>(g_wvt, DIM, g_xt, DIM,
                     mi * 128, ni * 256, DIM / BK2, g_vt, NTOK);
    } else {
        const int c2 = cta - 192;
        const int mi = c2 / 6, ni = c2 % 6;
        gemm_core_m(g_wkTh, g_wkTl, DIM, g_wqTh, g_wqTl, DIM,
                    mi * 128, ni * 128, DIM / BK, g_mt, DIM);
    }
}

// ---------------------------------------------------------------------------
// Kernel 3: Y = X * Mrow^T, 128x256 tf32 tiles. grid (3, 64).
// ---------------------------------------------------------------------------
__global__ __launch_bounds__(NTHREADS, 1)
void y_kernel()
{
    tf32_core<1>(g_xt, DIM, g_mt, DIM,
                 blockIdx.y * 128, blockIdx.x * 256, DIM / BK2,
                 g_yt, DIM);
}

// ---------------------------------------------------------------------------
// Kernel 4: scores S = Y X^T, 128x256 tiles, packed causal grid (72, 4).
// Tile (mi, j) kept iff j*256 <= mi*128+127  <=>  j <= mi/2.
// ---------------------------------------------------------------------------
__global__ __launch_bounds__(NTHREADS, 1)
void scores_kernel()
{
    const int t = blockIdx.x;
    int mi = 0, cum = 0;
    while (cum + (mi / 2 + 1) <= t) { cum += mi / 2 + 1; mi++; }
    const int j = t - cum;

    const int b = blockIdx.y;
    const size_t o = (size_t)b * SEQ * DIM;
    tf32_core<0>(g_yt + o, DIM, g_xt + o, DIM,
                 mi * 128, j * 256, DIM / BK2,
                 g_s + (size_t)b * SEQ * SEQ, SEQ);
}

// ---------------------------------------------------------------------------
// Kernel 5: causal softmax in place (tf32-rounded probs, bounded I/O).
// ---------------------------------------------------------------------------
__global__ __launch_bounds__(NTHREADS)
void softmax_kernel()
{
    const int q = blockIdx.x, b = blockIdx.y;
    float* row = g_s + ((size_t)b * SEQ + q) * SEQ;
    const int nvalid = q + 1;
    const int zlim = (q & ~127) + 128;
    const int tid = threadIdx.x, lane = tid & 31, wid = tid >> 5;

    __shared__ float sred[8];

    const int e0 = 4 * tid, e1 = 4 * (tid + 256);
    float4 v0 = (e0 < nvalid) ? ((const float4*)row)[tid]
                              : make_float4(0.f, 0.f, 0.f, 0.f);
    float4 v1 = (e1 < nvalid) ? ((const float4*)row)[tid + 256]
                              : make_float4(0.f, 0.f, 0.f, 0.f);

    float f[8] = {v0.x, v0.y, v0.z, v0.w, v1.x, v1.y, v1.z, v1.w};
    int   ei[8] = {e0, e0 + 1, e0 + 2, e0 + 3, e1, e1 + 1, e1 + 2, e1 + 3};

    float mx = -INFINITY;
#pragma unroll
    for (int j = 0; j < 8; j++)
        if (ei[j] < nvalid) mx = fmaxf(mx, f[j]);
#pragma unroll
    for (int o = 16; o > 0; o >>= 1)
        mx = fmaxf(mx, __shfl_xor_sync(0xffffffffu, mx, o));
    if (lane == 0) sred[wid] = mx;
    __syncthreads();
    mx = sred[0];
#pragma unroll
    for (int w = 1; w < 8; w++) mx = fmaxf(mx, sred[w]);

    float sum = 0.0f;
#pragma unroll
    for (int j = 0; j < 8; j++) {
        f[j] = (ei[j] < nvalid) ? expf((f[j] - mx) * SCALE) : 0.0f;
        sum += f[j];
    }
#pragma unroll
    for (int o = 16; o > 0; o >>= 1)
        sum += __shfl_xor_sync(0xffffffffu, sum, o);
    __syncthreads();
    if (lane == 0) sred[wid] = sum;
    __syncthreads();
    sum = 0.0f;
#pragma unroll
    for (int w = 0; w < 8; w++) sum += sred[w];
    const float inv = 1.0f / sum;

    if (e0 < zlim)
        ((float4*)row)[tid] = make_float4(to_tf32(f[0] * inv), to_tf32(f[1] * inv),
                                          to_tf32(f[2] * inv), to_tf32(f[3] * inv));
    if (e1 < zlim)
        ((float4*)row)[tid + 256] = make_float4(to_tf32(f[4] * inv), to_tf32(f[5] * inv),
                                                to_tf32(f[6] * inv), to_tf32(f[7] * inv));
}

// ---------------------------------------------------------------------------
// Kernel 6: O = P V via V^T, 128x256 tiles, k bounded by causal diagonal.
// grid (3, 16, 4)
// ---------------------------------------------------------------------------
__global__ __launch_bounds__(NTHREADS, 1)
void pv_kernel(float* __restrict__ out)
{
    const int b = blockIdx.z;
    const int m0 = blockIdx.y * 128, n0 = blockIdx.x * 256;
    tf32_core<0>(g_s + (size_t)b * SEQ * SEQ, SEQ,
                 g_vt + (size_t)b * SEQ, NTOK,
                 m0, n0, (m0 + 128) / BK2,
                 out + (size_t)b * SEQ * DIM, DIM);
}

// ---------------------------------------------------------------------------
extern "C" void kernel_launch(void* const* d_in, const int* in_sizes, int n_in,
                              void* d_out, int out_size)
{
    const float* x  = (const float*)d_in[0];
    const float* wq = (const float*)d_in[1];
    const float* wk = (const float*)d_in[2];
    const float* wv = (const float*)d_in[3];
    float* out = (float*)d_out;

    cudaFuncSetAttribute(vm_kernel,     cudaFuncAttributeMaxDynamicSharedMemorySize, W_SMEM);
    cudaFuncSetAttribute(y_kernel,      cudaFuncAttributeMaxDynamicSharedMemorySize, W_SMEM);
    cudaFuncSetAttribute(scores_kernel, cudaFuncAttributeMaxDynamicSharedMemorySize, W_SMEM);
    cudaFuncSetAttribute(pv_kernel,     cudaFuncAttributeMaxDynamicSharedMemorySize, W_SMEM);

    const int ntot = NX4 + NW4;
    convert_kernel<<<(ntot + NTHREADS - 1) / NTHREADS, NTHREADS>>>(x, wv);
    transpose_w_kernel<<<dim3(24, 24, 2), NTHREADS>>>(wq, wk);
    vm_kernel<<<228, NTHREADS, W_SMEM>>>();
    y_kernel<<<dim3(DIM / 256, NTOK / 128), NTHREADS, W_SMEM>>>();
    scores_kernel<<<dim3(72, BATCH), NTHREADS, W_SMEM>>>();
    softmax_kernel<<<dim3(SEQ, BATCH), NTHREADS>>>();
    pv_kernel<<<dim3(DIM / 256, SEQ / 128, BATCH), NTHREADS, W_SMEM>>>(out);
}

// round 14
// speedup vs baseline: 1.8543x; 1.8543x over previous
#include <cuda_runtime.h>
#include <cuda_bf16.h>
#include <cuda_fp16.h>
#include <math.h>
#include <stdint.h>

// ---------------------------------------------------------------------------
// Problem constants
// ---------------------------------------------------------------------------
#define BATCH 4
#define SEQ   2048
#define DIM   768
#define NTOK  (BATCH * SEQ)          // 8192
#define NTHREADS 256
#define SCALE 0.03608439182435161f   // 1/sqrt(768)

// bf16 GEMM tiling (M GEMM only): 128x128 tile, K chunk 32 bf16, SW64
#define BK 32
#define TILE_B  8192
#define STAGE_B (4 * TILE_B)         // 32 KB
#define SMEM_BYTES (2 * STAGE_B)     // 64 KB

// fp16 GEMM tiling: 128x128 CTA tile, K chunk of 64 halfs (128B rows, SW128)
#define HK 64
#define H_TILE_B  16384              // 128 rows * 128 B
#define H_STAGE_B (2 * H_TILE_B)     // 32 KB (A + B)
#define H_SMEM    (2 * H_STAGE_B)    // 64 KB double-buffered -> 2 CTAs/SM

#define SWZ(o)   ((o) ^ ((((uint32_t)(o)) >> 3) & 0x70))   // SW128
#define SWZ64(o) ((o) ^ ((((uint32_t)(o)) >> 3) & 0x30))   // SW64

// ---------------------------------------------------------------------------
// Scratch (__device__ globals; referenced ONLY from device code)
// ---------------------------------------------------------------------------
__device__ __align__(128) __half        g_x16[NTOK * DIM];     // x fp16
__device__ __align__(128) __nv_bfloat16 g_wqTh[DIM * DIM], g_wqTl[DIM * DIM];
__device__ __align__(128) __nv_bfloat16 g_wkTh[DIM * DIM], g_wkTl[DIM * DIM];
__device__ __align__(128) __half        g_wv16[DIM * DIM];     // wv fp16
__device__ __align__(128) __half        g_m16[DIM * DIM];      // Mrow fp16
__device__ __align__(128) __half        g_y16[NTOK * DIM];     // Y fp16
__device__ __align__(128) __half        g_vt16[DIM * NTOK];    // V^T fp16
__device__ __align__(128) float         g_s[(size_t)BATCH * SEQ * SEQ];   // S fp32
__device__ __align__(128) __half        g_p16[(size_t)BATCH * SEQ * SEQ]; // P fp16

// ---------------------------------------------------------------------------
// PTX helpers
// ---------------------------------------------------------------------------
__device__ __forceinline__ uint32_t smem_u32(const void* p) {
    uint32_t a;
    asm("{ .reg .u64 t; cvta.to.shared.u64 t, %1; cvt.u32.u64 %0, t; }"
        : "=r"(a) : "l"(p));
    return a;
}
__device__ __forceinline__ void cp16(uint32_t dst, const void* src) {
    asm volatile("cp.async.cg.shared.global [%0], [%1], 16;" :: "r"(dst), "l"(src));
}
__device__ __forceinline__ void cp_commit() {
    asm volatile("cp.async.commit_group;" ::: "memory");
}
template <int N>
__device__ __forceinline__ void cp_wait() {
    asm volatile("cp.async.wait_group %0;" :: "n"(N) : "memory");
}
__device__ __forceinline__ void ldsm4(uint32_t addr, uint32_t* r) {
    asm volatile("ldmatrix.sync.aligned.m8n8.x4.shared.b16 {%0,%1,%2,%3}, [%4];"
                 : "=r"(r[0]), "=r"(r[1]), "=r"(r[2]), "=r"(r[3]) : "r"(addr));
}
__device__ __forceinline__ void ldsm2(uint32_t addr, uint32_t* r) {
    asm volatile("ldmatrix.sync.aligned.m8n8.x2.shared.b16 {%0,%1}, [%2];"
                 : "=r"(r[0]), "=r"(r[1]) : "r"(addr));
}
__device__ __forceinline__ void mma16816bf(float* d, const uint32_t* a, const uint32_t* b) {
    asm volatile(
        "mma.sync.aligned.m16n8k16.row.col.f32.bf16.bf16.f32 "
        "{%0,%1,%2,%3}, {%4,%5,%6,%7}, {%8,%9}, {%0,%1,%2,%3};"
        : "+f"(d[0]), "+f"(d[1]), "+f"(d[2]), "+f"(d[3])
        : "r"(a[0]), "r"(a[1]), "r"(a[2]), "r"(a[3]), "r"(b[0]), "r"(b[1]));
}
__device__ __forceinline__ void mma16816h(float* d, const uint32_t* a, const uint32_t* b) {
    asm volatile(
        "mma.sync.aligned.m16n8k16.row.col.f32.f16.f16.f32 "
        "{%0,%1,%2,%3}, {%4,%5,%6,%7}, {%8,%9}, {%0,%1,%2,%3};"
        : "+f"(d[0]), "+f"(d[1]), "+f"(d[2]), "+f"(d[3])
        : "r"(a[0]), "r"(a[1]), "r"(a[2]), "r"(a[3]), "r"(b[0]), "r"(b[1]));
}

// ---------------------------------------------------------------------------
// 128x128 NT GEMM tile, split-bf16 3-term, BK=32, SW64.
// Used ONLY for the tiny M GEMM. Epilogue: fp16 out.
// ---------------------------------------------------------------------------
__device__ __forceinline__ void gemm_core_m(
    const __nv_bfloat16* __restrict__ Ah, const __nv_bfloat16* __restrict__ Al, int lda,
    const __nv_bfloat16* __restrict__ Bh, const __nv_bfloat16* __restrict__ Bl, int ldb,
    int m0, int n0, int nIter,
    __half* __restrict__ Of, int ldc)
{
    extern __shared__ char smem[];
    const uint32_t sbase = smem_u32(smem);
    const int tid  = threadIdx.x;
    const int lane = tid & 31;
    const int wid  = tid >> 5;
    const int wm   = wid >> 2;
    const int wn   = wid & 3;

    const __nv_bfloat16* A0h = Ah + (size_t)m0 * lda;
    const __nv_bfloat16* A0l = Al + (size_t)m0 * lda;
    const __nv_bfloat16* B0h = Bh + (size_t)n0 * ldb;
    const __nv_bfloat16* B0l = Bl + (size_t)n0 * ldb;

    auto load_tile = [&](int it) {
        const uint32_t db = sbase + (uint32_t)(it & 1) * STAGE_B;
        const int k0 = it * BK;
#pragma unroll
        for (int i = 0; i < 2; i++) {
            const int c = tid + i * NTHREADS;
            const int row = c >> 2, ch = c & 3;
            const uint32_t so = SWZ64((uint32_t)(row * 64 + ch * 16));
            const size_t ga = (size_t)row * lda + k0 + ch * 8;
            const size_t gb = (size_t)row * ldb + k0 + ch * 8;
            cp16(db + so,              A0h + ga);
            cp16(db + TILE_B + so,     A0l + ga);
            cp16(db + 2 * TILE_B + so, B0h + gb);
            cp16(db + 3 * TILE_B + so, B0l + gb);
        }
        cp_commit();
    };

    float acc[4][4][4];
#pragma unroll
    for (int i = 0; i < 4; i++)
#pragma unroll
        for (int j = 0; j < 4; j++)
#pragma unroll
            for (int v = 0; v < 4; v++) acc[i][j][v] = 0.0f;

    const uint32_t a_l = ((uint32_t)(lane & 15) << 6) + ((uint32_t)(lane >> 4) << 4);
    const uint32_t b_l = ((uint32_t)(lane & 7) << 6) + ((uint32_t)((lane >> 3) & 1) << 4);

    load_tile(0);
    load_tile(1);

    for (int it = 0; it < nIter; ++it) {
        if (it + 1 < nIter) cp_wait<1>(); else cp_wait<0>();
        __syncthreads();

        const uint32_t db = sbase + (uint32_t)(it & 1) * STAGE_B;
#pragma unroll
        for (int ks = 0; ks < 2; ks++) {
            uint32_t ah[4][4], al_[4][4], bh[4][2], bl_[4][2];
#pragma unroll
            for (int fm = 0; fm < 4; fm++) {
                const uint32_t sw = SWZ64(((uint32_t)(wm * 64 + fm * 16) << 6) +
                                          (uint32_t)(ks * 32) + a_l);
                ldsm4(db + sw, ah[fm]);
                ldsm4(db + TILE_B + sw, al_[fm]);
            }
#pragma unroll
            for (int fn = 0; fn < 4; fn++) {
                const uint32_t sw = SWZ64(((uint32_t)(wn * 32 + fn * 8) << 6) +
                                          (uint32_t)(ks * 32) + b_l);
                ldsm2(db + 2 * TILE_B + sw, bh[fn]);
                ldsm2(db + 3 * TILE_B + sw, bl_[fn]);
            }
#pragma unroll
            for (int fm = 0; fm < 4; fm++)
#pragma unroll
                for (int fn = 0; fn < 4; fn++)
                    mma16816bf(acc[fm][fn], ah[fm], bh[fn]);
#pragma unroll
            for (int fm = 0; fm < 4; fm++)
#pragma unroll
                for (int fn = 0; fn < 4; fn++)
                    mma16816bf(acc[fm][fn], ah[fm], bl_[fn]);
#pragma unroll
            for (int fm = 0; fm < 4; fm++)
#pragma unroll
                for (int fn = 0; fn < 4; fn++)
                    mma16816bf(acc[fm][fn], al_[fm], bh[fn]);
        }
        __syncthreads();
        if (it + 2 < nIter) load_tile(it + 2);
    }

    const int er = lane >> 2;
    const int ec = (lane & 3) * 2;
#pragma unroll
    for (int fm = 0; fm < 4; fm++) {
#pragma unroll
        for (int fn = 0; fn < 4; fn++) {
            const int r0 = m0 + wm * 64 + fm * 16 + er;
            const int r1 = r0 + 8;
            const int c  = n0 + wn * 32 + fn * 8 + ec;
            *(__half2*)(Of + (size_t)r0 * ldc + c) =
                __floats2half2_rn(acc[fm][fn][0], acc[fm][fn][1]);
            *(__half2*)(Of + (size_t)r1 * ldc + c) =
                __floats2half2_rn(acc[fm][fn][2], acc[fm][fn][3]);
        }
    }
}

// ---------------------------------------------------------------------------
// 128x128 NT GEMM tile, single-term FP16 (f32 accum), SW128, K chunk 64.
// Identical geometry to the validated round-4 bf16 core; 1/3 the MMAs.
// OUT 0: fp16 out.  OUT 1: fp32 out.
// ---------------------------------------------------------------------------
template <int OUT>
__device__ __forceinline__ void gemm_h(
    const __half* __restrict__ A, int lda,
    const __half* __restrict__ B, int ldb,
    int m0, int n0, int nIter,
    __half* __restrict__ Oh, float* __restrict__ Of, int ldc)
{
    extern __shared__ char smem[];
    const uint32_t sbase = smem_u32(smem);
    const int tid  = threadIdx.x;
    const int lane = tid & 31;
    const int wid  = tid >> 5;
    const int wm   = wid >> 2;
    const int wn   = wid & 3;

    const __half* A0 = A + (size_t)m0 * lda;
    const __half* B0 = B + (size_t)n0 * ldb;

    auto load_tile = [&](int it) {
        const uint32_t db = sbase + (uint32_t)(it & 1) * H_STAGE_B;
        const int k0 = it * HK;
#pragma unroll
        for (int i = 0; i < 4; i++) {
            const int c = tid + i * NTHREADS;        // 0..1023
            const int row = c >> 3, ch = c & 7;
            const uint32_t so = SWZ((uint32_t)(row * 128 + ch * 16));
            cp16(db + so,            A0 + (size_t)row * lda + k0 + ch * 8);
            cp16(db + H_TILE_B + so, B0 + (size_t)row * ldb + k0 + ch * 8);
        }
        cp_commit();
    };

    float acc[4][4][4];
#pragma unroll
    for (int i = 0; i < 4; i++)
#pragma unroll
        for (int j = 0; j < 4; j++)
#pragma unroll
            for (int v = 0; v < 4; v++) acc[i][j][v] = 0.0f;

    const uint32_t a_l = ((uint32_t)(lane & 15) << 7) + ((uint32_t)(lane >> 4) << 4);
    const uint32_t b_l = ((uint32_t)(lane & 7) << 7) + ((uint32_t)((lane >> 3) & 1) << 4);

    load_tile(0);
    load_tile(1);

    for (int it = 0; it < nIter; ++it) {
        if (it + 1 < nIter) cp_wait<1>(); else cp_wait<0>();
        __syncthreads();

        const uint32_t db = sbase + (uint32_t)(it & 1) * H_STAGE_B;
#pragma unroll
        for (int ks = 0; ks < 4; ks++) {           // 4 x k16 = 64
            uint32_t a[4][4], bb[4][2];
#pragma unroll
            for (int fm = 0; fm < 4; fm++) {
                const uint32_t sw = SWZ(((uint32_t)(wm * 64 + fm * 16) << 7) +
                                        (uint32_t)(ks * 32) + a_l);
                ldsm4(db + sw, a[fm]);
            }
#pragma unroll
            for (int fn = 0; fn < 4; fn++) {
                const uint32_t sw = SWZ(((uint32_t)(wn * 32 + fn * 8) << 7) +
                                        (uint32_t)(ks * 32) + b_l);
                ldsm2(db + H_TILE_B + sw, bb[fn]);
            }
#pragma unroll
            for (int fm = 0; fm < 4; fm++)
#pragma unroll
                for (int fn = 0; fn < 4; fn++)
                    mma16816h(acc[fm][fn], a[fm], bb[fn]);
        }
        __syncthreads();
        if (it + 2 < nIter) load_tile(it + 2);
    }

    const int er = lane >> 2;
    const int ec = (lane & 3) * 2;
#pragma unroll
    for (int fm = 0; fm < 4; fm++) {
#pragma unroll
        for (int fn = 0; fn < 4; fn++) {
            const int r0 = m0 + wm * 64 + fm * 16 + er;
            const int r1 = r0 + 8;
            const int c  = n0 + wn * 32 + fn * 8 + ec;
            if (OUT == 1) {
                *(float2*)(Of + (size_t)r0 * ldc + c) = make_float2(acc[fm][fn][0], acc[fm][fn][1]);
                *(float2*)(Of + (size_t)r1 * ldc + c) = make_float2(acc[fm][fn][2], acc[fm][fn][3]);
            } else {
                *(__half2*)(Oh + (size_t)r0 * ldc + c) =
                    __floats2half2_rn(acc[fm][fn][0], acc[fm][fn][1]);
                *(__half2*)(Oh + (size_t)r1 * ldc + c) =
                    __floats2half2_rn(acc[fm][fn][2], acc[fm][fn][3]);
            }
        }
    }
}

// ---------------------------------------------------------------------------
// Kernel 0: convert. x -> fp16; wv -> fp16.
// ---------------------------------------------------------------------------
#define NX4 (NTOK * DIM / 4)
#define NW4 (DIM * DIM / 4)

__global__ __launch_bounds__(NTHREADS)
void convert_kernel(const float* __restrict__ x, const float* __restrict__ wv)
{
    const int i = blockIdx.x * NTHREADS + threadIdx.x;
    if (i < NX4) {
        const float4 v = ((const float4*)x)[i];
        ((__half2*)g_x16)[2 * i]     = __floats2half2_rn(v.x, v.y);
        ((__half2*)g_x16)[2 * i + 1] = __floats2half2_rn(v.z, v.w);
    } else if (i < NX4 + NW4) {
        const int j = i - NX4;
        const float4 v = ((const float4*)wv)[j];
        ((__half2*)g_wv16)[2 * j]     = __floats2half2_rn(v.x, v.y);
        ((__half2*)g_wv16)[2 * j + 1] = __floats2half2_rn(v.z, v.w);
    }
}

// ---------------------------------------------------------------------------
// Kernel 1: tiled transpose wq, wk -> bf16 hi/lo pairs of W^T (for M GEMM).
// ---------------------------------------------------------------------------
__global__ __launch_bounds__(NTHREADS)
void transpose_w_kernel(const float* __restrict__ wq, const float* __restrict__ wk)
{
    __shared__ float t[32][33];
    const float* src = blockIdx.z ? wk : wq;
    __nv_bfloat16* oh = blockIdx.z ? g_wkTh : g_wqTh;
    __nv_bfloat16* ol = blockIdx.z ? g_wkTl : g_wqTl;
    const int tx = threadIdx.x & 31, ty = threadIdx.x >> 5;
    const int c0 = blockIdx.x * 32, r0 = blockIdx.y * 32;
#pragma unroll
    for (int i = 0; i < 4; i++)
        t[ty + i * 8][tx] = src[(size_t)(r0 + ty + i * 8) * DIM + c0 + tx];
    __syncthreads();
#pragma unroll
    for (int i = 0; i < 4; i++) {
        const int d = c0 + ty + i * 8;
        const int e = r0 + tx;
        const float v = t[tx][ty + i * 8];
        const __nv_bfloat16 h = __float2bfloat16(v);
        oh[(size_t)d * DIM + e] = h;
        ol[(size_t)d * DIM + e] = __float2bfloat16(v - __bfloat162float(h));
    }
}

// ---------------------------------------------------------------------------
// Kernel 2: fused V + M.
//   CTA < 384:  V^T = Wv X^T, fp16 single-term, out g_vt16
//   CTA >= 384: Mrow = Wk^T x Wq^T (3-term bf16), out g_m16 (fp16)
// ---------------------------------------------------------------------------
__global__ __launch_bounds__(NTHREADS, 2)
void vm_kernel()
{
    const int cta = blockIdx.x;
    if (cta < 384) {
        const int mi = cta / 64, ni = cta % 64;
        gemm_h<0>(g_wv16, DIM, g_x16, DIM,
                  mi * 128, ni * 128, DIM / HK, g_vt16, nullptr, NTOK);
    } else {
        const int c2 = cta - 384;
        const int mi = c2 / 6, ni = c2 % 6;
        gemm_core_m(g_wkTh, g_wkTl, DIM, g_wqTh, g_wqTl, DIM,
                    mi * 128, ni * 128, DIM / BK, g_m16, DIM);
    }
}

// ---------------------------------------------------------------------------
// Kernel 3: Y = X * Mrow^T, fp16 single-term. grid (6, 64).
// ---------------------------------------------------------------------------
__global__ __launch_bounds__(NTHREADS, 2)
void y_kernel()
{
    gemm_h<0>(g_x16, DIM, g_m16, DIM,
              blockIdx.y * 128, blockIdx.x * 128, DIM / HK,
              g_y16, nullptr, DIM);
}

// ---------------------------------------------------------------------------
// Kernel 4: scores S = Y X^T (fp32 out), packed triangle grid (136, 4).
// ---------------------------------------------------------------------------
__global__ __launch_bounds__(NTHREADS, 2)
void scores_kernel()
{
    const int t = blockIdx.x;
    int mi = (int)((sqrtf(8.0f * (float)t + 1.0f) - 1.0f) * 0.5f);
    while ((mi + 1) * (mi + 2) / 2 <= t) mi++;
    while (mi * (mi + 1) / 2 > t) mi--;
    const int ni = t - mi * (mi + 1) / 2;

    const int b = blockIdx.y;
    const size_t o = (size_t)b * SEQ * DIM;
    gemm_h<1>(g_y16 + o, DIM, g_x16 + o, DIM,
              mi * 128, ni * 128, DIM / HK,
              nullptr, g_s + (size_t)b * SEQ * SEQ, SEQ);
}

// ---------------------------------------------------------------------------
// Kernel 5: causal softmax: S fp32 in -> P fp16 out, bounded I/O.
// ---------------------------------------------------------------------------
__global__ __launch_bounds__(NTHREADS)
void softmax_kernel()
{
    const int q = blockIdx.x, b = blockIdx.y;
    const float* row = g_s + ((size_t)b * SEQ + q) * SEQ;
    __half* prow = g_p16 + ((size_t)b * SEQ + q) * SEQ;
    const int nvalid = q + 1;
    const int zlim = (q & ~127) + 128;
    const int tid = threadIdx.x, lane = tid & 31, wid = tid >> 5;

    __shared__ float sred[8];

    const int e0 = 4 * tid, e1 = 4 * (tid + 256);
    float4 v0 = (e0 < nvalid) ? ((const float4*)row)[tid]
                              : make_float4(0.f, 0.f, 0.f, 0.f);
    float4 v1 = (e1 < nvalid) ? ((const float4*)row)[tid + 256]
                              : make_float4(0.f, 0.f, 0.f, 0.f);

    float f[8] = {v0.x, v0.y, v0.z, v0.w, v1.x, v1.y, v1.z, v1.w};
    int   ei[8] = {e0, e0 + 1, e0 + 2, e0 + 3, e1, e1 + 1, e1 + 2, e1 + 3};

    float mx = -INFINITY;
#pragma unroll
    for (int j = 0; j < 8; j++)
        if (ei[j] < nvalid) mx = fmaxf(mx, f[j]);
#pragma unroll
    for (int o = 16; o > 0; o >>= 1)
        mx = fmaxf(mx, __shfl_xor_sync(0xffffffffu, mx, o));
    if (lane == 0) sred[wid] = mx;
    __syncthreads();
    mx = sred[0];
#pragma unroll
    for (int w = 1; w < 8; w++) mx = fmaxf(mx, sred[w]);

    float sum = 0.0f;
#pragma unroll
    for (int j = 0; j < 8; j++) {
        f[j] = (ei[j] < nvalid) ? expf((f[j] - mx) * SCALE) : 0.0f;
        sum += f[j];
    }
#pragma unroll
    for (int o = 16; o > 0; o >>= 1)
        sum += __shfl_xor_sync(0xffffffffu, sum, o);
    __syncthreads();
    if (lane == 0) sred[wid] = sum;
    __syncthreads();
    sum = 0.0f;
#pragma unroll
    for (int w = 0; w < 8; w++) sum += sred[w];
    const float inv = 1.0f / sum;

    if (e0 < zlim) {
        *(__half2*)(prow + e0)     = __floats2half2_rn(f[0] * inv, f[1] * inv);
        *(__half2*)(prow + e0 + 2) = __floats2half2_rn(f[2] * inv, f[3] * inv);
    }
    if (e1 < zlim) {
        *(__half2*)(prow + e1)     = __floats2half2_rn(f[4] * inv, f[5] * inv);
        *(__half2*)(prow + e1 + 2) = __floats2half2_rn(f[6] * inv, f[7] * inv);
    }
}

// ---------------------------------------------------------------------------
// Kernel 6: O = P V via V^T, fp16 single-term, k bounded by causal diagonal.
// Longest tiles scheduled first (mi reversed).
// ---------------------------------------------------------------------------
__global__ __launch_bounds__(NTHREADS, 2)
void pv_kernel(float* __restrict__ out)
{
    const int b = blockIdx.z;
    const int mi = 15 - blockIdx.y;           // longest-first
    const int m0 = mi * 128, n0 = blockIdx.x * 128;
    gemm_h<1>(g_p16 + (size_t)b * SEQ * SEQ, SEQ,
              g_vt16 + (size_t)b * SEQ, NTOK,
              m0, n0, (m0 + 128) / HK,
              nullptr, out + (size_t)b * SEQ * DIM, DIM);
}

// ---------------------------------------------------------------------------
extern "C" void kernel_launch(void* const* d_in, const int* in_sizes, int n_in,
                              void* d_out, int out_size)
{
    const float* x  = (const float*)d_in[0];
    const float* wq = (const float*)d_in[1];
    const float* wk = (const float*)d_in[2];
    const float* wv = (const float*)d_in[3];
    float* out = (float*)d_out;

    cudaFuncSetAttribute(vm_kernel,     cudaFuncAttributeMaxDynamicSharedMemorySize, H_SMEM);
    cudaFuncSetAttribute(y_kernel,      cudaFuncAttributeMaxDynamicSharedMemorySize, H_SMEM);
    cudaFuncSetAttribute(scores_kernel, cudaFuncAttributeMaxDynamicSharedMemorySize, H_SMEM);
    cudaFuncSetAttribute(pv_kernel,     cudaFuncAttributeMaxDynamicSharedMemorySize, H_SMEM);

    const int ntot = NX4 + NW4;
    convert_kernel<<<(ntot + NTHREADS - 1) / NTHREADS, NTHREADS>>>(x, wv);
    transpose_w_kernel<<<dim3(24, 24, 2), NTHREADS>>>(wq, wk);
    vm_kernel<<<420, NTHREADS, H_SMEM>>>();
    y_kernel<<<dim3(DIM / 128, NTOK / 128), NTHREADS, H_SMEM>>>();
    scores_kernel<<<dim3(136, BATCH), NTHREADS, H_SMEM>>>();
    softmax_kernel<<<dim3(SEQ, BATCH), NTHREADS>>>();
    pv_kernel<<<dim3(DIM / 128, SEQ / 128, BATCH), NTHREADS, H_SMEM>>>(out);
}

// round 15
// speedup vs baseline: 2.0435x; 1.1020x over previous
#include <cuda_runtime.h>
#include <cuda_fp16.h>
#include <math.h>
#include <stdint.h>

// ---------------------------------------------------------------------------
// Problem constants
// ---------------------------------------------------------------------------
#define BATCH 4
#define SEQ   2048
#define DIM   768
#define NTOK  (BATCH * SEQ)          // 8192
#define NTHREADS 256
#define SCALE 0.03608439182435161f   // 1/sqrt(768)

// fp16 GEMM tiling: 128x128 CTA tile, K chunk of 64 halfs (128B rows, SW128)
#define HK 64
#define H_TILE_B  16384              // 128 rows * 128 B
#define H_STAGE_B (2 * H_TILE_B)     // 32 KB (A + B)
#define H_SMEM    (2 * H_STAGE_B)    // 64 KB double-buffered -> 2 CTAs/SM

#define SWZ(o) ((o) ^ ((((uint32_t)(o)) >> 3) & 0x70))     // SW128

// ---------------------------------------------------------------------------
// Scratch (__device__ globals; referenced ONLY from device code)
// ---------------------------------------------------------------------------
__device__ __align__(128) __half g_x16[NTOK * DIM];       // x fp16
__device__ __align__(128) __half g_wqT16[DIM * DIM];      // Wq^T fp16
__device__ __align__(128) __half g_wkT16[DIM * DIM];      // Wk^T fp16
__device__ __align__(128) __half g_wv16[DIM * DIM];       // wv fp16
__device__ __align__(128) __half g_m16[DIM * DIM];        // Mrow fp16
__device__ __align__(128) __half g_y16[NTOK * DIM];       // Y fp16
__device__ __align__(128) __half g_vt16[DIM * NTOK];      // V^T fp16
__device__ __align__(128) float  g_s[(size_t)BATCH * SEQ * SEQ];   // S fp32
__device__ __align__(128) __half g_p16[(size_t)BATCH * SEQ * SEQ]; // P fp16

// ---------------------------------------------------------------------------
// PTX helpers
// ---------------------------------------------------------------------------
__device__ __forceinline__ uint32_t smem_u32(const void* p) {
    uint32_t a;
    asm("{ .reg .u64 t; cvta.to.shared.u64 t, %1; cvt.u32.u64 %0, t; }"
        : "=r"(a) : "l"(p));
    return a;
}
__device__ __forceinline__ void cp16(uint32_t dst, const void* src) {
    asm volatile("cp.async.cg.shared.global [%0], [%1], 16;" :: "r"(dst), "l"(src));
}
__device__ __forceinline__ void cp_commit() {
    asm volatile("cp.async.commit_group;" ::: "memory");
}
template <int N>
__device__ __forceinline__ void cp_wait() {
    asm volatile("cp.async.wait_group %0;" :: "n"(N) : "memory");
}
__device__ __forceinline__ void ldsm4(uint32_t addr, uint32_t* r) {
    asm volatile("ldmatrix.sync.aligned.m8n8.x4.shared.b16 {%0,%1,%2,%3}, [%4];"
                 : "=r"(r[0]), "=r"(r[1]), "=r"(r[2]), "=r"(r[3]) : "r"(addr));
}
__device__ __forceinline__ void ldsm2(uint32_t addr, uint32_t* r) {
    asm volatile("ldmatrix.sync.aligned.m8n8.x2.shared.b16 {%0,%1}, [%2];"
                 : "=r"(r[0]), "=r"(r[1]) : "r"(addr));
}
__device__ __forceinline__ void mma16816h(float* d, const uint32_t* a, const uint32_t* b) {
    asm volatile(
        "mma.sync.aligned.m16n8k16.row.col.f32.f16.f16.f32 "
        "{%0,%1,%2,%3}, {%4,%5,%6,%7}, {%8,%9}, {%0,%1,%2,%3};"
        : "+f"(d[0]), "+f"(d[1]), "+f"(d[2]), "+f"(d[3])
        : "r"(a[0]), "r"(a[1]), "r"(a[2]), "r"(a[3]), "r"(b[0]), "r"(b[1]));
}

// ---------------------------------------------------------------------------
// 128x128 NT GEMM tile, single-term FP16 (f32 accum), SW128, K chunk 64.
// OUT 0: fp16 out.  OUT 1: fp32 out.
// ---------------------------------------------------------------------------
template <int OUT>
__device__ __forceinline__ void gemm_h(
    const __half* __restrict__ A, int lda,
    const __half* __restrict__ B, int ldb,
    int m0, int n0, int nIter,
    __half* __restrict__ Oh, float* __restrict__ Of, int ldc)
{
    extern __shared__ char smem[];
    const uint32_t sbase = smem_u32(smem);
    const int tid  = threadIdx.x;
    const int lane = tid & 31;
    const int wid  = tid >> 5;
    const int wm   = wid >> 2;
    const int wn   = wid & 3;

    const __half* A0 = A + (size_t)m0 * lda;
    const __half* B0 = B + (size_t)n0 * ldb;

    auto load_tile = [&](int it) {
        const uint32_t db = sbase + (uint32_t)(it & 1) * H_STAGE_B;
        const int k0 = it * HK;
#pragma unroll
        for (int i = 0; i < 4; i++) {
            const int c = tid + i * NTHREADS;        // 0..1023
            const int row = c >> 3, ch = c & 7;
            const uint32_t so = SWZ((uint32_t)(row * 128 + ch * 16));
            cp16(db + so,            A0 + (size_t)row * lda + k0 + ch * 8);
            cp16(db + H_TILE_B + so, B0 + (size_t)row * ldb + k0 + ch * 8);
        }
        cp_commit();
    };

    float acc[4][4][4];
#pragma unroll
    for (int i = 0; i < 4; i++)
#pragma unroll
        for (int j = 0; j < 4; j++)
#pragma unroll
            for (int v = 0; v < 4; v++) acc[i][j][v] = 0.0f;

    const uint32_t a_l = ((uint32_t)(lane & 15) << 7) + ((uint32_t)(lane >> 4) << 4);
    const uint32_t b_l = ((uint32_t)(lane & 7) << 7) + ((uint32_t)((lane >> 3) & 1) << 4);

    load_tile(0);
    load_tile(1);

    for (int it = 0; it < nIter; ++it) {
        if (it + 1 < nIter) cp_wait<1>(); else cp_wait<0>();
        __syncthreads();

        const uint32_t db = sbase + (uint32_t)(it & 1) * H_STAGE_B;
#pragma unroll
        for (int ks = 0; ks < 4; ks++) {           // 4 x k16 = 64
            uint32_t a[4][4], bb[4][2];
#pragma unroll
            for (int fm = 0; fm < 4; fm++) {
                const uint32_t sw = SWZ(((uint32_t)(wm * 64 + fm * 16) << 7) +
                                        (uint32_t)(ks * 32) + a_l);
                ldsm4(db + sw, a[fm]);
            }
#pragma unroll
            for (int fn = 0; fn < 4; fn++) {
                const uint32_t sw = SWZ(((uint32_t)(wn * 32 + fn * 8) << 7) +
                                        (uint32_t)(ks * 32) + b_l);
                ldsm2(db + H_TILE_B + sw, bb[fn]);
            }
#pragma unroll
            for (int fm = 0; fm < 4; fm++)
#pragma unroll
                for (int fn = 0; fn < 4; fn++)
                    mma16816h(acc[fm][fn], a[fm], bb[fn]);
        }
        __syncthreads();
        if (it + 2 < nIter) load_tile(it + 2);
    }

    const int er = lane >> 2;
    const int ec = (lane & 3) * 2;
#pragma unroll
    for (int fm = 0; fm < 4; fm++) {
#pragma unroll
        for (int fn = 0; fn < 4; fn++) {
            const int r0 = m0 + wm * 64 + fm * 16 + er;
            const int r1 = r0 + 8;
            const int c  = n0 + wn * 32 + fn * 8 + ec;
            if (OUT == 1) {
                *(float2*)(Of + (size_t)r0 * ldc + c) = make_float2(acc[fm][fn][0], acc[fm][fn][1]);
                *(float2*)(Of + (size_t)r1 * ldc + c) = make_float2(acc[fm][fn][2], acc[fm][fn][3]);
            } else {
                *(__half2*)(Oh + (size_t)r0 * ldc + c) =
                    __floats2half2_rn(acc[fm][fn][0], acc[fm][fn][1]);
                *(__half2*)(Oh + (size_t)r1 * ldc + c) =
                    __floats2half2_rn(acc[fm][fn][2], acc[fm][fn][3]);
            }
        }
    }
}

// ---------------------------------------------------------------------------
// Kernel 0: convert. x -> fp16; wv -> fp16.
// ---------------------------------------------------------------------------
#define NX4 (NTOK * DIM / 4)
#define NW4 (DIM * DIM / 4)

__global__ __launch_bounds__(NTHREADS)
void convert_kernel(const float* __restrict__ x, const float* __restrict__ wv)
{
    const int i = blockIdx.x * NTHREADS + threadIdx.x;
    if (i < NX4) {
        const float4 v = ((const float4*)x)[i];
        ((__half2*)g_x16)[2 * i]     = __floats2half2_rn(v.x, v.y);
        ((__half2*)g_x16)[2 * i + 1] = __floats2half2_rn(v.z, v.w);
    } else if (i < NX4 + NW4) {
        const int j = i - NX4;
        const float4 v = ((const float4*)wv)[j];
        ((__half2*)g_wv16)[2 * j]     = __floats2half2_rn(v.x, v.y);
        ((__half2*)g_wv16)[2 * j + 1] = __floats2half2_rn(v.z, v.w);
    }
}

// ---------------------------------------------------------------------------
// Kernel 1: tiled transpose wq, wk -> fp16 W^T.
// ---------------------------------------------------------------------------
__global__ __launch_bounds__(NTHREADS)
void transpose_w_kernel(const float* __restrict__ wq, const float* __restrict__ wk)
{
    __shared__ float t[32][33];
    const float* src = blockIdx.z ? wk : wq;
    __half* oT = blockIdx.z ? g_wkT16 : g_wqT16;
    const int tx = threadIdx.x & 31, ty = threadIdx.x >> 5;
    const int c0 = blockIdx.x * 32, r0 = blockIdx.y * 32;
#pragma unroll
    for (int i = 0; i < 4; i++)
        t[ty + i * 8][tx] = src[(size_t)(r0 + ty + i * 8) * DIM + c0 + tx];
    __syncthreads();
#pragma unroll
    for (int i = 0; i < 4; i++) {
        const int d = c0 + ty + i * 8;
        const int e = r0 + tx;
        oT[(size_t)d * DIM + e] = __float2half_rn(t[tx][ty + i * 8]);
    }
}

// ---------------------------------------------------------------------------
// Kernel 2: fused V + M, all single-term fp16 (uniform tile time).
//   CTA < 384:  V^T = Wv X^T, out g_vt16
//   CTA >= 384: Mrow = Wk^T Wq^T^T (NT), out g_m16
// ---------------------------------------------------------------------------
__global__ __launch_bounds__(NTHREADS, 2)
void vm_kernel()
{
    const int cta = blockIdx.x;
    if (cta < 384) {
        const int mi = cta / 64, ni = cta % 64;
        gemm_h<0>(g_wv16, DIM, g_x16, DIM,
                  mi * 128, ni * 128, DIM / HK, g_vt16, nullptr, NTOK);
    } else {
        const int c2 = cta - 384;
        const int mi = c2 / 6, ni = c2 % 6;
        gemm_h<0>(g_wkT16, DIM, g_wqT16, DIM,
                  mi * 128, ni * 128, DIM / HK, g_m16, nullptr, DIM);
    }
}

// ---------------------------------------------------------------------------
// Kernel 3: Y = X * Mrow^T, fp16 single-term. grid (6, 64).
// ---------------------------------------------------------------------------
__global__ __launch_bounds__(NTHREADS, 2)
void y_kernel()
{
    gemm_h<0>(g_x16, DIM, g_m16, DIM,
              blockIdx.y * 128, blockIdx.x * 128, DIM / HK,
              g_y16, nullptr, DIM);
}

// ---------------------------------------------------------------------------
// Kernel 4: scores S = Y X^T (fp32 out), packed triangle grid (136, 4).
// ---------------------------------------------------------------------------
__global__ __launch_bounds__(NTHREADS, 2)
void scores_kernel()
{
    const int t = blockIdx.x;
    int mi = (int)((sqrtf(8.0f * (float)t + 1.0f) - 1.0f) * 0.5f);
    while ((mi + 1) * (mi + 2) / 2 <= t) mi++;
    while (mi * (mi + 1) / 2 > t) mi--;
    const int ni = t - mi * (mi + 1) / 2;

    const int b = blockIdx.y;
    const size_t o = (size_t)b * SEQ * DIM;
    gemm_h<1>(g_y16 + o, DIM, g_x16 + o, DIM,
              mi * 128, ni * 128, DIM / HK,
              nullptr, g_s + (size_t)b * SEQ * SEQ, SEQ);
}

// ---------------------------------------------------------------------------
// Kernel 5: causal softmax: S fp32 in -> P fp16 out, bounded I/O.
// ---------------------------------------------------------------------------
__global__ __launch_bounds__(NTHREADS)
void softmax_kernel()
{
    const int q = blockIdx.x, b = blockIdx.y;
    const float* row = g_s + ((size_t)b * SEQ + q) * SEQ;
    __half* prow = g_p16 + ((size_t)b * SEQ + q) * SEQ;
    const int nvalid = q + 1;
    const int zlim = (q & ~127) + 128;
    const int tid = threadIdx.x, lane = tid & 31, wid = tid >> 5;

    __shared__ float sred[8];

    const int e0 = 4 * tid, e1 = 4 * (tid + 256);
    float4 v0 = (e0 < nvalid) ? ((const float4*)row)[tid]
                              : make_float4(0.f, 0.f, 0.f, 0.f);
    float4 v1 = (e1 < nvalid) ? ((const float4*)row)[tid + 256]
                              : make_float4(0.f, 0.f, 0.f, 0.f);

    float f[8] = {v0.x, v0.y, v0.z, v0.w, v1.x, v1.y, v1.z, v1.w};
    int   ei[8] = {e0, e0 + 1, e0 + 2, e0 + 3, e1, e1 + 1, e1 + 2, e1 + 3};

    float mx = -INFINITY;
#pragma unroll
    for (int j = 0; j < 8; j++)
        if (ei[j] < nvalid) mx = fmaxf(mx, f[j]);
#pragma unroll
    for (int o = 16; o > 0; o >>= 1)
        mx = fmaxf(mx, __shfl_xor_sync(0xffffffffu, mx, o));
    if (lane == 0) sred[wid] = mx;
    __syncthreads();
    mx = sred[0];
#pragma unroll
    for (int w = 1; w < 8; w++) mx = fmaxf(mx, sred[w]);

    float sum = 0.0f;
#pragma unroll
    for (int j = 0; j < 8; j++) {
        f[j] = (ei[j] < nvalid) ? expf((f[j] - mx) * SCALE) : 0.0f;
        sum += f[j];
    }
#pragma unroll
    for (int o = 16; o > 0; o >>= 1)
        sum += __shfl_xor_sync(0xffffffffu, sum, o);
    __syncthreads();
    if (lane == 0) sred[wid] = sum;
    __syncthreads();
    sum = 0.0f;
#pragma unroll
    for (int w = 0; w < 8; w++) sum += sred[w];
    const float inv = 1.0f / sum;

    if (e0 < zlim) {
        *(__half2*)(prow + e0)     = __floats2half2_rn(f[0] * inv, f[1] * inv);
        *(__half2*)(prow + e0 + 2) = __floats2half2_rn(f[2] * inv, f[3] * inv);
    }
    if (e1 < zlim) {
        *(__half2*)(prow + e1)     = __floats2half2_rn(f[4] * inv, f[5] * inv);
        *(__half2*)(prow + e1 + 2) = __floats2half2_rn(f[6] * inv, f[7] * inv);
    }
}

// ---------------------------------------------------------------------------
// Kernel 6: O = P V via V^T, fp16 single-term, k bounded by causal diagonal.
// Longest tiles scheduled first (mi reversed).
// ---------------------------------------------------------------------------
__global__ __launch_bounds__(NTHREADS, 2)
void pv_kernel(float* __restrict__ out)
{
    const int b = blockIdx.z;
    const int mi = 15 - blockIdx.y;           // longest-first
    const int m0 = mi * 128, n0 = blockIdx.x * 128;
    gemm_h<1>(g_p16 + (size_t)b * SEQ * SEQ, SEQ,
              g_vt16 + (size_t)b * SEQ, NTOK,
              m0, n0, (m0 + 128) / HK,
              nullptr, out + (size_t)b * SEQ * DIM, DIM);
}

// ---------------------------------------------------------------------------
extern "C" void kernel_launch(void* const* d_in, const int* in_sizes, int n_in,
                              void* d_out, int out_size)
{
    const float* x  = (const float*)d_in[0];
    const float* wq = (const float*)d_in[1];
    const float* wk = (const float*)d_in[2];
    const float* wv = (const float*)d_in[3];
    float* out = (float*)d_out;

    cudaFuncSetAttribute(vm_kernel,     cudaFuncAttributeMaxDynamicSharedMemorySize, H_SMEM);
    cudaFuncSetAttribute(y_kernel,      cudaFuncAttributeMaxDynamicSharedMemorySize, H_SMEM);
    cudaFuncSetAttribute(scores_kernel, cudaFuncAttributeMaxDynamicSharedMemorySize, H_SMEM);
    cudaFuncSetAttribute(pv_kernel,     cudaFuncAttributeMaxDynamicSharedMemorySize, H_SMEM);

    const int ntot = NX4 + NW4;
    convert_kernel<<<(ntot + NTHREADS - 1) / NTHREADS, NTHREADS>>>(x, wv);
    transpose_w_kernel<<<dim3(24, 24, 2), NTHREADS>>>(wq, wk);
    vm_kernel<<<420, NTHREADS, H_SMEM>>>();
    y_kernel<<<dim3(DIM / 128, NTOK / 128), NTHREADS, H_SMEM>>>();
    scores_kernel<<<dim3(136, BATCH), NTHREADS, H_SMEM>>>();
    softmax_kernel<<<dim3(SEQ, BATCH), NTHREADS>>>();
    pv_kernel<<<dim3(DIM / 128, SEQ / 128, BATCH), NTHREADS, H_SMEM>>>(out);
}

// round 17
// speedup vs baseline: 2.0956x; 1.0255x over previous
#include <cuda_runtime.h>
#include <cuda_fp16.h>
#include <math.h>
#include <stdint.h>

// ---------------------------------------------------------------------------
// Problem constants
// ---------------------------------------------------------------------------
#define BATCH 4
#define SEQ   2048
#define DIM   768
#define NTOK  (BATCH * SEQ)          // 8192
#define NTHREADS 256
#define SCALE 0.03608439182435161f   // 1/sqrt(768)

// fp16 GEMM tiling: 128x128 CTA tile, K chunk of 64 halfs (128B rows, SW128)
#define HK 64
#define H_TILE_B  16384              // 128 rows * 128 B
#define H_STAGE_B (2 * H_TILE_B)     // 32 KB (A + B)
#define H_SMEM    (2 * H_STAGE_B)    // 64 KB double-buffered -> 2 CTAs/SM

#define SWZ(o) ((o) ^ ((((uint32_t)(o)) >> 3) & 0x70))     // SW128

// ---------------------------------------------------------------------------
// Scratch (__device__ globals; referenced ONLY from device code)
// ---------------------------------------------------------------------------
__device__ __align__(128) __half g_x16[NTOK * DIM];       // x fp16
__device__ __align__(128) __half g_wqT16[DIM * DIM];      // Wq^T fp16
__device__ __align__(128) __half g_wkT16[DIM * DIM];      // Wk^T fp16
__device__ __align__(128) __half g_wv16[DIM * DIM];       // wv fp16
__device__ __align__(128) __half g_m16[DIM * DIM];        // Mrow fp16
__device__ __align__(128) __half g_y16[NTOK * DIM];       // Y fp16
__device__ __align__(128) __half g_vt16[DIM * NTOK];      // V^T fp16
__device__ __align__(128) float  g_s[(size_t)BATCH * SEQ * SEQ];   // S fp32
__device__ __align__(128) __half g_p16[(size_t)BATCH * SEQ * SEQ]; // P fp16
__device__ int g_mdone;                                   // M-tile semaphore

// ---------------------------------------------------------------------------
// PTX helpers
// ---------------------------------------------------------------------------
__device__ __forceinline__ uint32_t smem_u32(const void* p) {
    uint32_t a;
    asm("{ .reg .u64 t; cvta.to.shared.u64 t, %1; cvt.u32.u64 %0, t; }"
        : "=r"(a) : "l"(p));
    return a;
}
__device__ __forceinline__ void cp16(uint32_t dst, const void* src) {
    asm volatile("cp.async.cg.shared.global [%0], [%1], 16;" :: "r"(dst), "l"(src));
}
__device__ __forceinline__ void cp_commit() {
    asm volatile("cp.async.commit_group;" ::: "memory");
}
template <int N>
__device__ __forceinline__ void cp_wait() {
    asm volatile("cp.async.wait_group %0;" :: "n"(N) : "memory");
}
__device__ __forceinline__ void ldsm4(uint32_t addr, uint32_t* r) {
    asm volatile("ldmatrix.sync.aligned.m8n8.x4.shared.b16 {%0,%1,%2,%3}, [%4];"
                 : "=r"(r[0]), "=r"(r[1]), "=r"(r[2]), "=r"(r[3]) : "r"(addr));
}
__device__ __forceinline__ void ldsm2(uint32_t addr, uint32_t* r) {
    asm volatile("ldmatrix.sync.aligned.m8n8.x2.shared.b16 {%0,%1}, [%2];"
                 : "=r"(r[0]), "=r"(r[1]) : "r"(addr));
}
__device__ __forceinline__ void mma16816h(float* d, const uint32_t* a, const uint32_t* b) {
    asm volatile(
        "mma.sync.aligned.m16n8k16.row.col.f32.f16.f16.f32 "
        "{%0,%1,%2,%3}, {%4,%5,%6,%7}, {%8,%9}, {%0,%1,%2,%3};"
        : "+f"(d[0]), "+f"(d[1]), "+f"(d[2]), "+f"(d[3])
        : "r"(a[0]), "r"(a[1]), "r"(a[2]), "r"(a[3]), "r"(b[0]), "r"(b[1]));
}

// ---------------------------------------------------------------------------
// 128x128 NT GEMM tile, single-term FP16 (f32 accum), SW128, K chunk 64.
// OUT 0: fp16 out.  OUT 1: fp32 out.
// ---------------------------------------------------------------------------
template <int OUT>
__device__ __forceinline__ void gemm_h(
    const __half* __restrict__ A, int lda,
    const __half* __restrict__ B, int ldb,
    int m0, int n0, int nIter,
    __half* __restrict__ Oh, float* __restrict__ Of, int ldc)
{
    extern __shared__ char smem[];
    const uint32_t sbase = smem_u32(smem);
    const int tid  = threadIdx.x;
    const int lane = tid & 31;
    const int wid  = tid >> 5;
    const int wm   = wid >> 2;
    const int wn   = wid & 3;

    const __half* A0 = A + (size_t)m0 * lda;
    const __half* B0 = B + (size_t)n0 * ldb;

    auto load_tile = [&](int it) {
        const uint32_t db = sbase + (uint32_t)(it & 1) * H_STAGE_B;
        const int k0 = it * HK;
#pragma unroll
        for (int i = 0; i < 4; i++) {
            const int c = tid + i * NTHREADS;        // 0..1023
            const int row = c >> 3, ch = c & 7;
            const uint32_t so = SWZ((uint32_t)(row * 128 + ch * 16));
            cp16(db + so,            A0 + (size_t)row * lda + k0 + ch * 8);
            cp16(db + H_TILE_B + so, B0 + (size_t)row * ldb + k0 + ch * 8);
        }
        cp_commit();
    };

    float acc[4][4][4];
#pragma unroll
    for (int i = 0; i < 4; i++)
#pragma unroll
        for (int j = 0; j < 4; j++)
#pragma unroll
            for (int v = 0; v < 4; v++) acc[i][j][v] = 0.0f;

    const uint32_t a_l = ((uint32_t)(lane & 15) << 7) + ((uint32_t)(lane >> 4) << 4);
    const uint32_t b_l = ((uint32_t)(lane & 7) << 7) + ((uint32_t)((lane >> 3) & 1) << 4);

    load_tile(0);
    load_tile(1);

    for (int it = 0; it < nIter; ++it) {
        if (it + 1 < nIter) cp_wait<1>(); else cp_wait<0>();
        __syncthreads();

        const uint32_t db = sbase + (uint32_t)(it & 1) * H_STAGE_B;
#pragma unroll
        for (int ks = 0; ks < 4; ks++) {           // 4 x k16 = 64
            uint32_t a[4][4], bb[4][2];
#pragma unroll
            for (int fm = 0; fm < 4; fm++) {
                const uint32_t sw = SWZ(((uint32_t)(wm * 64 + fm * 16) << 7) +
                                        (uint32_t)(ks * 32) + a_l);
                ldsm4(db + sw, a[fm]);
            }
#pragma unroll
            for (int fn = 0; fn < 4; fn++) {
                const uint32_t sw = SWZ(((uint32_t)(wn * 32 + fn * 8) << 7) +
                                        (uint32_t)(ks * 32) + b_l);
                ldsm2(db + H_TILE_B + sw, bb[fn]);
            }
#pragma unroll
            for (int fm = 0; fm < 4; fm++)
#pragma unroll
                for (int fn = 0; fn < 4; fn++)
                    mma16816h(acc[fm][fn], a[fm], bb[fn]);
        }
        __syncthreads();
        if (it + 2 < nIter) load_tile(it + 2);
    }

    const int er = lane >> 2;
    const int ec = (lane & 3) * 2;
#pragma unroll
    for (int fm = 0; fm < 4; fm++) {
#pragma unroll
        for (int fn = 0; fn < 4; fn++) {
            const int r0 = m0 + wm * 64 + fm * 16 + er;
            const int r1 = r0 + 8;
            const int c  = n0 + wn * 32 + fn * 8 + ec;
            if (OUT == 1) {
                *(float2*)(Of + (size_t)r0 * ldc + c) = make_float2(acc[fm][fn][0], acc[fm][fn][1]);
                *(float2*)(Of + (size_t)r1 * ldc + c) = make_float2(acc[fm][fn][2], acc[fm][fn][3]);
            } else {
                *(__half2*)(Oh + (size_t)r0 * ldc + c) =
                    __floats2half2_rn(acc[fm][fn][0], acc[fm][fn][1]);
                *(__half2*)(Oh + (size_t)r1 * ldc + c) =
                    __floats2half2_rn(acc[fm][fn][2], acc[fm][fn][3]);
            }
        }
    }
}

// ---------------------------------------------------------------------------
// Kernel 0: fused prep. bid < NCONV: fp32->fp16 convert of x/wv.
// bid >= NCONV: 32x32 tiled transpose of wq/wk -> fp16 W^T.
// Also resets the M semaphore (block 0).
// ---------------------------------------------------------------------------
#define NX4 (NTOK * DIM / 4)
#define NW4 (DIM * DIM / 4)
#define NCONV ((NX4 + NW4) / NTHREADS)     // 6720 blocks, exact
#define NTRANS (24 * 24 * 2)               // 1152 blocks

__global__ __launch_bounds__(NTHREADS)
void prep_kernel(const float* __restrict__ x,  const float* __restrict__ wq,
                 const float* __restrict__ wk, const float* __restrict__ wv)
{
    __shared__ float t[32][33];
    const int bid = blockIdx.x;
    if (bid == 0 && threadIdx.x == 0) g_mdone = 0;

    if (bid < NCONV) {
        const int i = bid * NTHREADS + threadIdx.x;
        if (i < NX4) {
            const float4 v = ((const float4*)x)[i];
            ((__half2*)g_x16)[2 * i]     = __floats2half2_rn(v.x, v.y);
            ((__half2*)g_x16)[2 * i + 1] = __floats2half2_rn(v.z, v.w);
        } else {
            const int j = i - NX4;
            const float4 v = ((const float4*)wv)[j];
            ((__half2*)g_wv16)[2 * j]     = __floats2half2_rn(v.x, v.y);
            ((__half2*)g_wv16)[2 * j + 1] = __floats2half2_rn(v.z, v.w);
        }
    } else {
        const int tb = bid - NCONV;
        const int z  = tb / 576;
        const int by = (tb % 576) / 24;
        const int bx = tb % 24;
        const float* src = z ? wk : wq;
        __half* oT = z ? g_wkT16 : g_wqT16;
        const int tx = threadIdx.x & 31, ty = threadIdx.x >> 5;
        const int c0 = bx * 32, r0 = by * 32;
#pragma unroll
        for (int i = 0; i < 4; i++)
            t[ty + i * 8][tx] = src[(size_t)(r0 + ty + i * 8) * DIM + c0 + tx];
        __syncthreads();
#pragma unroll
        for (int i = 0; i < 4; i++) {
            const int d = c0 + ty + i * 8;
            const int e = r0 + tx;
            oT[(size_t)d * DIM + e] = __float2half_rn(t[tx][ty + i * 8]);
        }
    }
}

// ---------------------------------------------------------------------------
// Kernel 1: fused M + V + Y in one launch.
//   bids [0,36):    Mrow = Wk^T Wq^T^T, out g_m16; signals g_mdone.
//   bids [36,420):  V^T = Wv X^T, out g_vt16.
//   bids [420,804): Y = X Mrow^T; spins on g_mdone==36 first.
// Deadlock-free: waiters (wave>=2) depend only on bids 0-35 (wave-1
// deterministic residency); M finishes with wave 1.
// ---------------------------------------------------------------------------
__global__ __launch_bounds__(NTHREADS, 2)
void vmy_kernel()
{
    const int cta = blockIdx.x;
    if (cta < 36) {
        const int mi = cta / 6, ni = cta % 6;
        gemm_h<0>(g_wkT16, DIM, g_wqT16, DIM,
                  mi * 128, ni * 128, DIM / HK, g_m16, nullptr, DIM);
        __threadfence();
        __syncthreads();
        if (threadIdx.x == 0) atomicAdd(&g_mdone, 1);
    } else if (cta < 420) {
        const int c2 = cta - 36;
        const int mi = c2 / 64, ni = c2 % 64;
        gemm_h<0>(g_wv16, DIM, g_x16, DIM,
                  mi * 128, ni * 128, DIM / HK, g_vt16, nullptr, NTOK);
    } else {
        if (threadIdx.x == 0) {
            while (atomicAdd(&g_mdone, 0) < 36) { }
        }
        __syncthreads();
        __threadfence();
        const int c3 = cta - 420;
        const int mi = c3 / 6, ni = c3 % 6;
        gemm_h<0>(g_x16, DIM, g_m16, DIM,
                  mi * 128, ni * 128, DIM / HK, g_y16, nullptr, DIM);
    }
}

// ---------------------------------------------------------------------------
// Kernel 2: scores S = Y X^T (fp32 out), packed triangle grid (136, 4).
// ---------------------------------------------------------------------------
__global__ __launch_bounds__(NTHREADS, 2)
void scores_kernel()
{
    const int t = blockIdx.x;
    int mi = (int)((sqrtf(8.0f * (float)t + 1.0f) - 1.0f) * 0.5f);
    while ((mi + 1) * (mi + 2) / 2 <= t) mi++;
    while (mi * (mi + 1) / 2 > t) mi--;
    const int ni = t - mi * (mi + 1) / 2;

    const int b = blockIdx.y;
    const size_t o = (size_t)b * SEQ * DIM;
    gemm_h<1>(g_y16 + o, DIM, g_x16 + o, DIM,
              mi * 128, ni * 128, DIM / HK,
              nullptr, g_s + (size_t)b * SEQ * SEQ, SEQ);
}

// ---------------------------------------------------------------------------
// Kernel 3: causal softmax: S fp32 in -> P fp16 out, bounded I/O.
// ---------------------------------------------------------------------------
__global__ __launch_bounds__(NTHREADS)
void softmax_kernel()
{
    const int q = blockIdx.x, b = blockIdx.y;
    const float* row = g_s + ((size_t)b * SEQ + q) * SEQ;
    __half* prow = g_p16 + ((size_t)b * SEQ + q) * SEQ;
    const int nvalid = q + 1;
    const int zlim = (q & ~127) + 128;
    const int tid = threadIdx.x, lane = tid & 31, wid = tid >> 5;

    __shared__ float sred[8];

    const int e0 = 4 * tid, e1 = 4 * (tid + 256);
    float4 v0 = (e0 < nvalid) ? ((const float4*)row)[tid]
                              : make_float4(0.f, 0.f, 0.f, 0.f);
    float4 v1 = (e1 < nvalid) ? ((const float4*)row)[tid + 256]
                              : make_float4(0.f, 0.f, 0.f, 0.f);

    float f[8] = {v0.x, v0.y, v0.z, v0.w, v1.x, v1.y, v1.z, v1.w};
    int   ei[8] = {e0, e0 + 1, e0 + 2, e0 + 3, e1, e1 + 1, e1 + 2, e1 + 3};

    float mx = -INFINITY;
#pragma unroll
    for (int j = 0; j < 8; j++)
        if (ei[j] < nvalid) mx = fmaxf(mx, f[j]);
#pragma unroll
    for (int o = 16; o > 0; o >>= 1)
        mx = fmaxf(mx, __shfl_xor_sync(0xffffffffu, mx, o));
    if (lane == 0) sred[wid] = mx;
    __syncthreads();
    mx = sred[0];
#pragma unroll
    for (int w = 1; w < 8; w++) mx = fmaxf(mx, sred[w]);

    float sum = 0.0f;
#pragma unroll
    for (int j = 0; j < 8; j++) {
        f[j] = (ei[j] < nvalid) ? expf((f[j] - mx) * SCALE) : 0.0f;
        sum += f[j];
    }
#pragma unroll
    for (int o = 16; o > 0; o >>= 1)
        sum += __shfl_xor_sync(0xffffffffu, sum, o);
    __syncthreads();
    if (lane == 0) sred[wid] = sum;
    __syncthreads();
    sum = 0.0f;
#pragma unroll
    for (int w = 0; w < 8; w++) sum += sred[w];
    const float inv = 1.0f / sum;

    if (e0 < zlim) {
        *(__half2*)(prow + e0)     = __floats2half2_rn(f[0] * inv, f[1] * inv);
        *(__half2*)(prow + e0 + 2) = __floats2half2_rn(f[2] * inv, f[3] * inv);
    }
    if (e1 < zlim) {
        *(__half2*)(prow + e1)     = __floats2half2_rn(f[4] * inv, f[5] * inv);
        *(__half2*)(prow + e1 + 2) = __floats2half2_rn(f[6] * inv, f[7] * inv);
    }
}

// ---------------------------------------------------------------------------
// Kernel 4: O = P V via V^T, fp16 single-term, k bounded by causal diagonal.
// Longest tiles scheduled first (mi reversed).
// ---------------------------------------------------------------------------
__global__ __launch_bounds__(NTHREADS, 2)
void pv_kernel(float* __restrict__ out)
{
    const int b = blockIdx.z;
    const int mi = 15 - blockIdx.y;           // longest-first
    const int m0 = mi * 128, n0 = blockIdx.x * 128;
    gemm_h<1>(g_p16 + (size_t)b * SEQ * SEQ, SEQ,
              g_vt16 + (size_t)b * SEQ, NTOK,
              m0, n0, (m0 + 128) / HK,
              nullptr, out + (size_t)b * SEQ * DIM, DIM);
}

// ---------------------------------------------------------------------------
extern "C" void kernel_launch(void* const* d_in, const int* in_sizes, int n_in,
                              void* d_out, int out_size)
{
    const float* x  = (const float*)d_in[0];
    const float* wq = (const float*)d_in[1];
    const float* wk = (const float*)d_in[2];
    const float* wv = (const float*)d_in[3];
    float* out = (float*)d_out;

    cudaFuncSetAttribute(vmy_kernel,    cudaFuncAttributeMaxDynamicSharedMemorySize, H_SMEM);
    cudaFuncSetAttribute(scores_kernel, cudaFuncAttributeMaxDynamicSharedMemorySize, H_SMEM);
    cudaFuncSetAttribute(pv_kernel,     cudaFuncAttributeMaxDynamicSharedMemorySize, H_SMEM);

    prep_kernel<<<NCONV + NTRANS, NTHREADS>>>(x, wq, wk, wv);
    vmy_kernel<<<804, NTHREADS, H_SMEM>>>();
    scores_kernel<<<dim3(136, BATCH), NTHREADS, H_SMEM>>>();
    softmax_kernel<<<dim3(SEQ, BATCH), NTHREADS>>>();
    pv_kernel<<<dim3(DIM / 128, SEQ / 128, BATCH), NTHREADS, H_SMEM>>>(out);
}